// round 10
// baseline (speedup 1.0000x reference)
#include <cuda_runtime.h>

// SelfAttention: B=2, L=2048, E=512, H=8, D=64
//   q/k/v = X @ W.T + b            (3 GEMMs 4096x512x512, head-major out)
//   S = q k^T; mask==0 -> -1e20; softmax(S/sqrt(512)); O = P v   (flash-fused)
//   out = O @ Wo.T + bo            (GEMM 4096x512x512)
// All fp32; inner loops use Blackwell f32x2 packed FMA (2x FFMA throughput).

#define cB 2
#define cL 2048
#define cE 512
#define cH 8
#define cD 64

__device__ float g_Q[cB * cH * cL * cD];
__device__ float g_K[cB * cH * cL * cD];
__device__ float g_V[cB * cH * cL * cD];
__device__ float g_O[cB * cL * cE];

__device__ __forceinline__ void fma2(unsigned long long& d,
                                     unsigned long long a,
                                     unsigned long long b) {
    asm("fma.rn.f32x2 %0, %1, %2, %0;" : "+l"(d) : "l"(a), "l"(b));
}
__device__ __forceinline__ void mul2(unsigned long long& d, unsigned long long a) {
    asm("mul.rn.f32x2 %0, %0, %1;" : "+l"(d) : "l"(a));
}
__device__ __forceinline__ unsigned long long pk2(float lo, float hi) {
    unsigned long long r;
    asm("mov.b64 %0, {%1, %2};" : "=l"(r) : "f"(lo), "f"(hi));
    return r;
}
__device__ __forceinline__ float2 upk2(unsigned long long v) {
    float2 f;
    asm("mov.b64 {%0, %1}, %2;" : "=f"(f.x), "=f"(f.y) : "l"(v));
    return f;
}

// ---------------------------------------------------------------------------
// GEMM: Y[m,n] = sum_k X[m,k] * W[n,k] + bias[n]
// M=4096, N=512, K=512. Block tile 128x64, BK=16, 256 threads, 8x4 micro-tile.
// which: 0/1/2 -> write head-major [B,H,L,D] into g_Q/g_K/g_V; 3 -> plain into
// dst, with X read from g_O.
// ---------------------------------------------------------------------------
__global__ __launch_bounds__(256, 2)
void gemm_kernel(const float* __restrict__ X, const float* __restrict__ W,
                 const float* __restrict__ bias, float* __restrict__ dst,
                 const int which)
{
    __shared__ __align__(16) float As[128][20];  // [m][k], pad->20 (odd quads)
    __shared__ __align__(16) float Bs[64][20];   // [n][k]
    const float* __restrict__ Xp = (which == 3) ? g_O : X;

    const int tid = threadIdx.x;
    const int ty = tid >> 4;           // 0..15 (row group)
    const int tx = tid & 15;           // 0..15 (col lane)
    const int m0 = blockIdx.y * 128;
    const int n0 = blockIdx.x * 64;

    unsigned long long acc[8][4];      // 8 rows x 4 cols, f32x2 pairs over k
#pragma unroll
    for (int i = 0; i < 8; i++)
#pragma unroll
        for (int j = 0; j < 4; j++) acc[i][j] = 0ull;

    for (int kb = 0; kb < cE; kb += 16) {
#pragma unroll
        for (int it = 0; it < 2; it++) {
            int idx = tid + it * 256;
            int row = idx >> 2, q = idx & 3;
            *(float4*)&As[row][q * 4] =
                *(const float4*)(Xp + (size_t)(m0 + row) * cE + kb + q * 4);
        }
        {
            int row = tid >> 2, q = tid & 3;
            *(float4*)&Bs[row][q * 4] =
                *(const float4*)(W + (size_t)(n0 + row) * cE + kb + q * 4);
        }
        __syncthreads();
#pragma unroll
        for (int k4 = 0; k4 < 4; k4++) {
            ulonglong2 b2[4];
#pragma unroll
            for (int j = 0; j < 4; j++)
                b2[j] = *(const ulonglong2*)&Bs[j * 16 + tx][k4 * 4];
#pragma unroll
            for (int i = 0; i < 8; i++) {
                ulonglong2 a2 = *(const ulonglong2*)&As[ty * 8 + i][k4 * 4];
#pragma unroll
                for (int j = 0; j < 4; j++) {
                    fma2(acc[i][j], a2.x, b2[j].x);
                    fma2(acc[i][j], a2.y, b2[j].y);
                }
            }
        }
        __syncthreads();
    }

    float bj[4];
#pragma unroll
    for (int j = 0; j < 4; j++) bj[j] = bias[n0 + j * 16 + tx];

    if (which == 3) {
#pragma unroll
        for (int i = 0; i < 8; i++) {
            int m = m0 + ty * 8 + i;
#pragma unroll
            for (int j = 0; j < 4; j++) {
                float2 p = upk2(acc[i][j]);
                dst[(size_t)m * cE + n0 + j * 16 + tx] = p.x + p.y + bj[j];
            }
        }
    } else {
        float* G = (which == 0) ? g_Q : (which == 1) ? g_K : g_V;
        const int h = n0 >> 6;  // BN=64 == D, one head per block column
#pragma unroll
        for (int i = 0; i < 8; i++) {
            int m = m0 + ty * 8 + i;
            int b = m >> 11;            // /L
            int l = m & (cL - 1);
            size_t base = (((size_t)(b * cH + h)) * cL + l) * cD;
#pragma unroll
            for (int j = 0; j < 4; j++) {
                float2 p = upk2(acc[i][j]);
                G[base + j * 16 + tx] = p.x + p.y + bj[j];
            }
        }
    }
}

// ---------------------------------------------------------------------------
// Flash attention, fp32. One block = one (b,h) and a 64-row q-tile.
// 256 threads (16x16). S tile rows r=i*16+ty, cols c=j*16+tx (strided mapping
// -> conflict-free SMEM reads). O tile rows r=i*16+ty, cols d=tx*4+j (float4).
// ---------------------------------------------------------------------------
#define SROW 68
#define SMEM_ATTN (4 * 64 * SROW * 4)

__global__ __launch_bounds__(256, 2)
void attn_kernel(const int* __restrict__ mask)
{
    extern __shared__ float sm[];
    float* Qs = sm;                    // [64][68]
    float* Ks = sm + 64 * SROW;
    float* Vs = sm + 2 * 64 * SROW;
    float* Ps = sm + 3 * 64 * SROW;

    const int tid = threadIdx.x;
    const int ty = tid >> 4;
    const int tx = tid & 15;
    const int q0 = blockIdx.x * 64;
    const int bh = blockIdx.y;         // b*H + h
    const int b = bh >> 3;
    const int h = bh & 7;
    const float* gq = g_Q + (size_t)bh * cL * cD;
    const float* gk = g_K + (size_t)bh * cL * cD;
    const float* gv = g_V + (size_t)bh * cL * cD;
    const size_t mbase = (size_t)b * cL * cL;

#pragma unroll
    for (int it = 0; it < 4; it++) {
        int idx = tid + it * 256;
        int row = idx >> 4, q = idx & 15;
        *(float4*)&Qs[row * SROW + q * 4] =
            *(const float4*)(gq + (size_t)(q0 + row) * cD + q * 4);
    }

    unsigned long long accO[4][2];
    float mrow[4], lrow[4];
#pragma unroll
    for (int i = 0; i < 4; i++) {
        accO[i][0] = 0ull; accO[i][1] = 0ull;
        mrow[i] = -1e30f;
        lrow[i] = 0.f;
    }
    const float rs = 0.04419417382415922f;       // 1/sqrt(512)
    const float MASKED = -4.4194173824159216e18f; // -1e20/sqrt(512)

    for (int kt = 0; kt < cL / 64; kt++) {
        const int k0 = kt * 64;
        __syncthreads();   // prior iteration's reads of Ks/Vs/Ps complete
#pragma unroll
        for (int it = 0; it < 4; it++) {
            int idx = tid + it * 256;
            int row = idx >> 4, q = idx & 15;
            *(float4*)&Ks[row * SROW + q * 4] =
                *(const float4*)(gk + (size_t)(k0 + row) * cD + q * 4);
            *(float4*)&Vs[row * SROW + q * 4] =
                *(const float4*)(gv + (size_t)(k0 + row) * cD + q * 4);
        }
        // Prefetch mask for this tile (latency hidden under S-GEMM)
        int mv[4][4];
#pragma unroll
        for (int i = 0; i < 4; i++)
#pragma unroll
            for (int j = 0; j < 4; j++)
                mv[i][j] = mask[mbase + (size_t)(q0 + i * 16 + ty) * cL +
                                k0 + j * 16 + tx];
        __syncthreads();

        // S = Q @ K^T  (f32x2 pairs over d, reduce pair at the end)
        unsigned long long accS[4][4];
#pragma unroll
        for (int i = 0; i < 4; i++)
#pragma unroll
            for (int j = 0; j < 4; j++) accS[i][j] = 0ull;

#pragma unroll 4
        for (int d4 = 0; d4 < 16; d4++) {
            ulonglong2 b2[4];
#pragma unroll
            for (int j = 0; j < 4; j++)
                b2[j] = *(const ulonglong2*)&Ks[(j * 16 + tx) * SROW + d4 * 4];
#pragma unroll
            for (int i = 0; i < 4; i++) {
                ulonglong2 a2 =
                    *(const ulonglong2*)&Qs[(i * 16 + ty) * SROW + d4 * 4];
#pragma unroll
                for (int j = 0; j < 4; j++) {
                    fma2(accS[i][j], a2.x, b2[j].x);
                    fma2(accS[i][j], a2.y, b2[j].y);
                }
            }
        }

        // mask + scale + online softmax (row = 16 lanes sharing ty)
#pragma unroll
        for (int i = 0; i < 4; i++) {
            const int r = i * 16 + ty;
            float s[4];
#pragma unroll
            for (int j = 0; j < 4; j++) {
                float2 p = upk2(accS[i][j]);
                s[j] = (mv[i][j] != 0) ? (p.x + p.y) * rs : MASKED;
            }
            float mx = fmaxf(fmaxf(s[0], s[1]), fmaxf(s[2], s[3]));
#pragma unroll
            for (int o = 8; o > 0; o >>= 1)
                mx = fmaxf(mx, __shfl_xor_sync(0xffffffffu, mx, o));
            const float mn = fmaxf(mrow[i], mx);
            const float fac = __expf(mrow[i] - mn);
            mrow[i] = mn;
            float rsum = 0.f;
#pragma unroll
            for (int j = 0; j < 4; j++) {
                float pv = __expf(s[j] - mn);
                Ps[r * SROW + j * 16 + tx] = pv;
                rsum += pv;
            }
#pragma unroll
            for (int o = 8; o > 0; o >>= 1)
                rsum += __shfl_xor_sync(0xffffffffu, rsum, o);
            lrow[i] = lrow[i] * fac + rsum;
            unsigned long long f2 = pk2(fac, fac);
            mul2(accO[i][0], f2);
            mul2(accO[i][1], f2);
        }
        __syncthreads();

        // O += P @ V
#pragma unroll 8
        for (int c = 0; c < 64; c++) {
            ulonglong2 v2 = *(const ulonglong2*)&Vs[c * SROW + tx * 4];
#pragma unroll
            for (int i = 0; i < 4; i++) {
                float pv = Ps[(i * 16 + ty) * SROW + c];
                unsigned long long p2 = pk2(pv, pv);
                fma2(accO[i][0], p2, v2.x);
                fma2(accO[i][1], p2, v2.y);
            }
        }
    }

    // epilogue: normalize, write interleaved [B, L, E] (E idx = h*D + d)
#pragma unroll
    for (int i = 0; i < 4; i++) {
        const float inv = 1.0f / lrow[i];
        float2 o0 = upk2(accO[i][0]);
        float2 o1 = upk2(accO[i][1]);
        float4 o = make_float4(o0.x * inv, o0.y * inv, o1.x * inv, o1.y * inv);
        const int row = q0 + i * 16 + ty;
        *(float4*)(g_O + ((size_t)(b * cL + row)) * cE + h * cD + tx * 4) = o;
    }
}

// ---------------------------------------------------------------------------
extern "C" void kernel_launch(void* const* d_in, const int* in_sizes, int n_in,
                              void* d_out, int out_size)
{
    const float* values = (const float*)d_in[0];
    const float* keys   = (const float*)d_in[1];
    const float* query  = (const float*)d_in[2];
    const int*   mask   = (const int*)d_in[3];
    const float* Wv = (const float*)d_in[4];
    const float* bv = (const float*)d_in[5];
    const float* Wk = (const float*)d_in[6];
    const float* bk = (const float*)d_in[7];
    const float* Wq = (const float*)d_in[8];
    const float* bq = (const float*)d_in[9];
    const float* Wo = (const float*)d_in[10];
    const float* bo = (const float*)d_in[11];
    float* out = (float*)d_out;

    const dim3 gg(cE / 64, (cB * cL) / 128);  // (8, 32)
    gemm_kernel<<<gg, 256>>>(query,  Wq, bq, nullptr, 0);  // -> g_Q
    gemm_kernel<<<gg, 256>>>(keys,   Wk, bk, nullptr, 1);  // -> g_K
    gemm_kernel<<<gg, 256>>>(values, Wv, bv, nullptr, 2);  // -> g_V

    cudaFuncSetAttribute(attn_kernel,
                         cudaFuncAttributeMaxDynamicSharedMemorySize,
                         SMEM_ATTN);
    attn_kernel<<<dim3(cL / 64, cB * cH), 256, SMEM_ATTN>>>(mask);

    gemm_kernel<<<gg, 256>>>(nullptr, Wo, bo, out, 3);     // g_O -> out
}

// round 11
// speedup vs baseline: 1.0006x; 1.0006x over previous
#include <cuda_runtime.h>

// SelfAttention: B=2, L=2048, E=512, H=8, D=64
//   q/k/v = X @ W.T + b            (3 GEMMs 4096x512x512, head-major out)
//   S = q k^T; mask==0 -> -1e20; softmax(S/sqrt(512)); O = P v   (flash-fused)
//   out = O @ Wo.T + bo            (GEMM 4096x512x512)
// All fp32; inner loops use Blackwell f32x2 packed FMA (2x FFMA throughput).

#define cB 2
#define cL 2048
#define cE 512
#define cH 8
#define cD 64

__device__ float g_Q[cB * cH * cL * cD];
__device__ float g_K[cB * cH * cL * cD];
__device__ float g_V[cB * cH * cL * cD];
__device__ float g_O[cB * cL * cE];

__device__ __forceinline__ void fma2(unsigned long long& d,
                                     unsigned long long a,
                                     unsigned long long b) {
    asm("fma.rn.f32x2 %0, %1, %2, %0;" : "+l"(d) : "l"(a), "l"(b));
}
__device__ __forceinline__ void mul2(unsigned long long& d, unsigned long long a) {
    asm("mul.rn.f32x2 %0, %0, %1;" : "+l"(d) : "l"(a));
}
__device__ __forceinline__ unsigned long long pk2(float lo, float hi) {
    unsigned long long r;
    asm("mov.b64 %0, {%1, %2};" : "=l"(r) : "f"(lo), "f"(hi));
    return r;
}
__device__ __forceinline__ float2 upk2(unsigned long long v) {
    float2 f;
    asm("mov.b64 {%0, %1}, %2;" : "=f"(f.x), "=f"(f.y) : "l"(v));
    return f;
}

// ---------------------------------------------------------------------------
// GEMM: Y[m,n] = sum_k X[m,k] * W[n,k] + bias[n]
// M=4096, N=512, K=512. Block tile 128x64, BK=16, 256 threads, 8x4 micro-tile.
// which: 0/1/2 -> write head-major [B,H,L,D] into g_Q/g_K/g_V; 3 -> plain into
// dst, with X read from g_O.
// ---------------------------------------------------------------------------
__global__ __launch_bounds__(256, 2)
void gemm_kernel(const float* __restrict__ X, const float* __restrict__ W,
                 const float* __restrict__ bias, float* __restrict__ dst,
                 const int which)
{
    __shared__ __align__(16) float As[128][20];  // [m][k], pad->20 (odd quads)
    __shared__ __align__(16) float Bs[64][20];   // [n][k]
    const float* __restrict__ Xp = (which == 3) ? g_O : X;

    const int tid = threadIdx.x;
    const int ty = tid >> 4;           // 0..15 (row group)
    const int tx = tid & 15;           // 0..15 (col lane)
    const int m0 = blockIdx.y * 128;
    const int n0 = blockIdx.x * 64;

    unsigned long long acc[8][4];      // 8 rows x 4 cols, f32x2 pairs over k
#pragma unroll
    for (int i = 0; i < 8; i++)
#pragma unroll
        for (int j = 0; j < 4; j++) acc[i][j] = 0ull;

    for (int kb = 0; kb < cE; kb += 16) {
#pragma unroll
        for (int it = 0; it < 2; it++) {
            int idx = tid + it * 256;
            int row = idx >> 2, q = idx & 3;
            *(float4*)&As[row][q * 4] =
                *(const float4*)(Xp + (size_t)(m0 + row) * cE + kb + q * 4);
        }
        {
            int row = tid >> 2, q = tid & 3;
            *(float4*)&Bs[row][q * 4] =
                *(const float4*)(W + (size_t)(n0 + row) * cE + kb + q * 4);
        }
        __syncthreads();
#pragma unroll
        for (int k4 = 0; k4 < 4; k4++) {
            ulonglong2 b2[4];
#pragma unroll
            for (int j = 0; j < 4; j++)
                b2[j] = *(const ulonglong2*)&Bs[j * 16 + tx][k4 * 4];
#pragma unroll
            for (int i = 0; i < 8; i++) {
                ulonglong2 a2 = *(const ulonglong2*)&As[ty * 8 + i][k4 * 4];
#pragma unroll
                for (int j = 0; j < 4; j++) {
                    fma2(acc[i][j], a2.x, b2[j].x);
                    fma2(acc[i][j], a2.y, b2[j].y);
                }
            }
        }
        __syncthreads();
    }

    float bj[4];
#pragma unroll
    for (int j = 0; j < 4; j++) bj[j] = bias[n0 + j * 16 + tx];

    if (which == 3) {
#pragma unroll
        for (int i = 0; i < 8; i++) {
            int m = m0 + ty * 8 + i;
#pragma unroll
            for (int j = 0; j < 4; j++) {
                float2 p = upk2(acc[i][j]);
                dst[(size_t)m * cE + n0 + j * 16 + tx] = p.x + p.y + bj[j];
            }
        }
    } else {
        float* G = (which == 0) ? g_Q : (which == 1) ? g_K : g_V;
        const int h = n0 >> 6;  // BN=64 == D, one head per block column
#pragma unroll
        for (int i = 0; i < 8; i++) {
            int m = m0 + ty * 8 + i;
            int b = m >> 11;            // /L
            int l = m & (cL - 1);
            size_t base = (((size_t)(b * cH + h)) * cL + l) * cD;
#pragma unroll
            for (int j = 0; j < 4; j++) {
                float2 p = upk2(acc[i][j]);
                G[base + j * 16 + tx] = p.x + p.y + bj[j];
            }
        }
    }
}

// ---------------------------------------------------------------------------
// Flash attention, fp32. One block = one (b,h) and a 64-row q-tile.
// 256 threads (16x16). S tile rows r=i*16+ty, cols c=j*16+tx (strided mapping
// -> conflict-free SMEM reads). O tile rows r=i*16+ty, cols d=tx*4+j (float4).
// ---------------------------------------------------------------------------
#define SROW 68
#define SMEM_ATTN (4 * 64 * SROW * 4)

__global__ __launch_bounds__(256, 2)
void attn_kernel(const int* __restrict__ mask)
{
    extern __shared__ float sm[];
    float* Qs = sm;                    // [64][68]
    float* Ks = sm + 64 * SROW;
    float* Vs = sm + 2 * 64 * SROW;
    float* Ps = sm + 3 * 64 * SROW;

    const int tid = threadIdx.x;
    const int ty = tid >> 4;
    const int tx = tid & 15;
    const int q0 = blockIdx.x * 64;
    const int bh = blockIdx.y;         // b*H + h
    const int b = bh >> 3;
    const int h = bh & 7;
    const float* gq = g_Q + (size_t)bh * cL * cD;
    const float* gk = g_K + (size_t)bh * cL * cD;
    const float* gv = g_V + (size_t)bh * cL * cD;
    const size_t mbase = (size_t)b * cL * cL;

#pragma unroll
    for (int it = 0; it < 4; it++) {
        int idx = tid + it * 256;
        int row = idx >> 4, q = idx & 15;
        *(float4*)&Qs[row * SROW + q * 4] =
            *(const float4*)(gq + (size_t)(q0 + row) * cD + q * 4);
    }

    unsigned long long accO[4][2];
    float mrow[4], lrow[4];
#pragma unroll
    for (int i = 0; i < 4; i++) {
        accO[i][0] = 0ull; accO[i][1] = 0ull;
        mrow[i] = -1e30f;
        lrow[i] = 0.f;
    }
    const float rs = 0.04419417382415922f;       // 1/sqrt(512)
    const float MASKED = -4.4194173824159216e18f; // -1e20/sqrt(512)

    for (int kt = 0; kt < cL / 64; kt++) {
        const int k0 = kt * 64;
        __syncthreads();   // prior iteration's reads of Ks/Vs/Ps complete
#pragma unroll
        for (int it = 0; it < 4; it++) {
            int idx = tid + it * 256;
            int row = idx >> 4, q = idx & 15;
            *(float4*)&Ks[row * SROW + q * 4] =
                *(const float4*)(gk + (size_t)(k0 + row) * cD + q * 4);
            *(float4*)&Vs[row * SROW + q * 4] =
                *(const float4*)(gv + (size_t)(k0 + row) * cD + q * 4);
        }
        // Prefetch mask for this tile (latency hidden under S-GEMM)
        int mv[4][4];
#pragma unroll
        for (int i = 0; i < 4; i++)
#pragma unroll
            for (int j = 0; j < 4; j++)
                mv[i][j] = mask[mbase + (size_t)(q0 + i * 16 + ty) * cL +
                                k0 + j * 16 + tx];
        __syncthreads();

        // S = Q @ K^T  (f32x2 pairs over d, reduce pair at the end)
        unsigned long long accS[4][4];
#pragma unroll
        for (int i = 0; i < 4; i++)
#pragma unroll
            for (int j = 0; j < 4; j++) accS[i][j] = 0ull;

#pragma unroll 4
        for (int d4 = 0; d4 < 16; d4++) {
            ulonglong2 b2[4];
#pragma unroll
            for (int j = 0; j < 4; j++)
                b2[j] = *(const ulonglong2*)&Ks[(j * 16 + tx) * SROW + d4 * 4];
#pragma unroll
            for (int i = 0; i < 4; i++) {
                ulonglong2 a2 =
                    *(const ulonglong2*)&Qs[(i * 16 + ty) * SROW + d4 * 4];
#pragma unroll
                for (int j = 0; j < 4; j++) {
                    fma2(accS[i][j], a2.x, b2[j].x);
                    fma2(accS[i][j], a2.y, b2[j].y);
                }
            }
        }

        // mask + scale + online softmax (row = 16 lanes sharing ty)
#pragma unroll
        for (int i = 0; i < 4; i++) {
            const int r = i * 16 + ty;
            float s[4];
#pragma unroll
            for (int j = 0; j < 4; j++) {
                float2 p = upk2(accS[i][j]);
                s[j] = (mv[i][j] != 0) ? (p.x + p.y) * rs : MASKED;
            }
            float mx = fmaxf(fmaxf(s[0], s[1]), fmaxf(s[2], s[3]));
#pragma unroll
            for (int o = 8; o > 0; o >>= 1)
                mx = fmaxf(mx, __shfl_xor_sync(0xffffffffu, mx, o));
            const float mn = fmaxf(mrow[i], mx);
            const float fac = __expf(mrow[i] - mn);
            mrow[i] = mn;
            float rsum = 0.f;
#pragma unroll
            for (int j = 0; j < 4; j++) {
                float pv = __expf(s[j] - mn);
                Ps[r * SROW + j * 16 + tx] = pv;
                rsum += pv;
            }
#pragma unroll
            for (int o = 8; o > 0; o >>= 1)
                rsum += __shfl_xor_sync(0xffffffffu, rsum, o);
            lrow[i] = lrow[i] * fac + rsum;
            unsigned long long f2 = pk2(fac, fac);
            mul2(accO[i][0], f2);
            mul2(accO[i][1], f2);
        }
        __syncthreads();

        // O += P @ V
#pragma unroll 8
        for (int c = 0; c < 64; c++) {
            ulonglong2 v2 = *(const ulonglong2*)&Vs[c * SROW + tx * 4];
#pragma unroll
            for (int i = 0; i < 4; i++) {
                float pv = Ps[(i * 16 + ty) * SROW + c];
                unsigned long long p2 = pk2(pv, pv);
                fma2(accO[i][0], p2, v2.x);
                fma2(accO[i][1], p2, v2.y);
            }
        }
    }

    // epilogue: normalize, write interleaved [B, L, E] (E idx = h*D + d)
#pragma unroll
    for (int i = 0; i < 4; i++) {
        const float inv = 1.0f / lrow[i];
        float2 o0 = upk2(accO[i][0]);
        float2 o1 = upk2(accO[i][1]);
        float4 o = make_float4(o0.x * inv, o0.y * inv, o1.x * inv, o1.y * inv);
        const int row = q0 + i * 16 + ty;
        *(float4*)(g_O + ((size_t)(b * cL + row)) * cE + h * cD + tx * 4) = o;
    }
}

// ---------------------------------------------------------------------------
extern "C" void kernel_launch(void* const* d_in, const int* in_sizes, int n_in,
                              void* d_out, int out_size)
{
    const float* values = (const float*)d_in[0];
    const float* keys   = (const float*)d_in[1];
    const float* query  = (const float*)d_in[2];
    const int*   mask   = (const int*)d_in[3];
    const float* Wv = (const float*)d_in[4];
    const float* bv = (const float*)d_in[5];
    const float* Wk = (const float*)d_in[6];
    const float* bk = (const float*)d_in[7];
    const float* Wq = (const float*)d_in[8];
    const float* bq = (const float*)d_in[9];
    const float* Wo = (const float*)d_in[10];
    const float* bo = (const float*)d_in[11];
    float* out = (float*)d_out;

    const dim3 gg(cE / 64, (cB * cL) / 128);  // (8, 32)
    gemm_kernel<<<gg, 256>>>(query,  Wq, bq, nullptr, 0);  // -> g_Q
    gemm_kernel<<<gg, 256>>>(keys,   Wk, bk, nullptr, 1);  // -> g_K
    gemm_kernel<<<gg, 256>>>(values, Wv, bv, nullptr, 2);  // -> g_V

    cudaFuncSetAttribute(attn_kernel,
                         cudaFuncAttributeMaxDynamicSharedMemorySize,
                         SMEM_ATTN);
    attn_kernel<<<dim3(cL / 64, cB * cH), 256, SMEM_ATTN>>>(mask);

    gemm_kernel<<<gg, 256>>>(nullptr, Wo, bo, out, 3);     // g_O -> out
}